// round 1
// baseline (speedup 1.0000x reference)
#include <cuda_runtime.h>
#include <math.h>

#define BB 2
#define SS_ 2048
#define DD 2048
#define HH 16
#define HD 128
#define M_TOT (BB * SS_)     // 4096
#define N_QKV (3 * DD)       // 6144

// Scratch (static device allocations are allowed; runtime allocs are not)
__device__ float g_qkv[M_TOT * N_QKV];   // ~100.7 MB : (b*s, 3*d) = q|k|v interleaved per row
__device__ float g_att[M_TOT * DD];      // ~33.6 MB  : attention output in (b, s, d) layout

// ---------------------------------------------------------------------------
// Tiled SGEMM: C[M,N] = A[M,K] @ W[K,N] + bias[N]
// BM=BN=128, BK=16, 256 threads, 8x8 microtile (split 4+4 fragments).
// M % 128 == 0, N % 128 == 0, K % 16 == 0 (all true for this problem).
// ---------------------------------------------------------------------------
__global__ __launch_bounds__(256) void sgemm_bias_kernel(
    const float* __restrict__ A, const float* __restrict__ Bm,
    const float* __restrict__ bias, float* __restrict__ C,
    int M, int N, int K)
{
    __shared__ float As[16][132];   // transposed: As[k][i], padded
    __shared__ float Bs[16][128];   // Bs[k][j]

    const int tid = threadIdx.x;
    const int tx = tid & 15;
    const int ty = tid >> 4;
    const int m0 = blockIdx.y * 128;
    const int n0 = blockIdx.x * 128;

    float acc[8][8];
#pragma unroll
    for (int i = 0; i < 8; i++)
#pragma unroll
        for (int j = 0; j < 8; j++) acc[i][j] = 0.f;

    for (int k0 = 0; k0 < K; k0 += 16) {
        // Load A tile 128x16 (transposed into As)
#pragma unroll
        for (int l = 0; l < 2; l++) {
            int idx = tid * 2 + l;          // 0..511 float4 slots
            int i   = idx >> 2;             // row within tile
            int kk  = (idx & 3) * 4;        // k offset
            float4 v = *reinterpret_cast<const float4*>(&A[(size_t)(m0 + i) * K + k0 + kk]);
            As[kk + 0][i] = v.x;
            As[kk + 1][i] = v.y;
            As[kk + 2][i] = v.z;
            As[kk + 3][i] = v.w;
        }
        // Load B tile 16x128
#pragma unroll
        for (int l = 0; l < 2; l++) {
            int idx = tid * 2 + l;
            int kk  = idx >> 5;             // 0..15
            int j   = (idx & 31) * 4;
            *reinterpret_cast<float4*>(&Bs[kk][j]) =
                *reinterpret_cast<const float4*>(&Bm[(size_t)(k0 + kk) * N + n0 + j]);
        }
        __syncthreads();

#pragma unroll
        for (int k = 0; k < 16; k++) {
            float4 a0 = *reinterpret_cast<const float4*>(&As[k][ty * 4]);
            float4 a1 = *reinterpret_cast<const float4*>(&As[k][64 + ty * 4]);
            float4 b0 = *reinterpret_cast<const float4*>(&Bs[k][tx * 4]);
            float4 b1 = *reinterpret_cast<const float4*>(&Bs[k][64 + tx * 4]);
            float a[8] = {a0.x, a0.y, a0.z, a0.w, a1.x, a1.y, a1.z, a1.w};
            float b[8] = {b0.x, b0.y, b0.z, b0.w, b1.x, b1.y, b1.z, b1.w};
#pragma unroll
            for (int ii = 0; ii < 8; ii++)
#pragma unroll
                for (int jj = 0; jj < 8; jj++)
                    acc[ii][jj] += a[ii] * b[jj];
        }
        __syncthreads();
    }

    // Epilogue with bias
#pragma unroll
    for (int ii = 0; ii < 8; ii++) {
        int r = m0 + ((ii < 4) ? (ty * 4 + ii) : (64 + ty * 4 + ii - 4));
#pragma unroll
        for (int jj = 0; jj < 8; jj++) {
            int c = n0 + ((jj < 4) ? (tx * 4 + jj) : (64 + tx * 4 + jj - 4));
            C[(size_t)r * N + c] = acc[ii][jj] + bias[c];
        }
    }
}

// ---------------------------------------------------------------------------
// Flash attention (fp32, online softmax, causal). One CTA = 64 queries of one
// (batch, head). 256 threads. Dynamic smem ~115.8 KB.
// ---------------------------------------------------------------------------
#define ATTN_SMEM_FLOATS (64 * 128 + 128 * 68 + 64 * 128 + 64 * 68 + 192)
#define ATTN_SMEM_BYTES  (ATTN_SMEM_FLOATS * 4)

__global__ __launch_bounds__(256) void flash_attn_kernel(
    const float* __restrict__ qkv, float* __restrict__ att)
{
    extern __shared__ float sm[];
    float* Qs    = sm;                      // [64][128]
    float* KT    = Qs + 64 * 128;           // [128][68]  (K transposed, padded)
    float* Vs    = KT + 128 * 68;           // [64][128]
    float* Sst   = Vs + 64 * 128;           // [64][68]
    float* row_m = Sst + 64 * 68;           // [64]
    float* row_l = row_m + 64;              // [64]
    float* row_c = row_l + 64;              // [64]

    const int tid = threadIdx.x;
    const int tx = tid & 15;
    const int ty = tid >> 4;
    const int qb = blockIdx.x;
    const int h  = blockIdx.y;
    const int b  = blockIdx.z;
    const int q0 = qb * 64;
    const float scale = 0.08838834764831845f;  // 1/sqrt(128)

    const int base = b * SS_ * N_QKV + h * HD;

    // Load Q tile (64x128)
#pragma unroll
    for (int l = 0; l < 8; l++) {
        int idx = tid + l * 256;           // float4 index, 0..2047
        int i   = idx >> 5;
        int d4  = (idx & 31) << 2;
        float4 v = *reinterpret_cast<const float4*>(&qkv[base + (q0 + i) * N_QKV + d4]);
        *reinterpret_cast<float4*>(&Qs[i * HD + d4]) = v;
    }
    if (tid < 64) { row_m[tid] = -INFINITY; row_l[tid] = 0.f; }

    float o[4][8];
#pragma unroll
    for (int ii = 0; ii < 4; ii++)
#pragma unroll
        for (int jj = 0; jj < 8; jj++) o[ii][jj] = 0.f;

    for (int kb = 0; kb <= qb; kb++) {
        __syncthreads();   // protect smem tiles from previous iteration readers
        const int k0 = kb * 64;

        // Load K (transposed into KT) and V tiles
#pragma unroll
        for (int l = 0; l < 8; l++) {
            int idx = tid + l * 256;
            int j   = idx >> 5;
            int d4  = (idx & 31) << 2;
            const float* src = &qkv[base + (k0 + j) * N_QKV];
            float4 kv = *reinterpret_cast<const float4*>(&src[DD + d4]);
            KT[(d4 + 0) * 68 + j] = kv.x;
            KT[(d4 + 1) * 68 + j] = kv.y;
            KT[(d4 + 2) * 68 + j] = kv.z;
            KT[(d4 + 3) * 68 + j] = kv.w;
            float4 vv = *reinterpret_cast<const float4*>(&src[2 * DD + d4]);
            *reinterpret_cast<float4*>(&Vs[j * HD + d4]) = vv;
        }
        __syncthreads();

        // S = Q K^T (each thread 4x4)
        float s[4][4];
#pragma unroll
        for (int ii = 0; ii < 4; ii++)
#pragma unroll
            for (int jj = 0; jj < 4; jj++) s[ii][jj] = 0.f;

        for (int k = 0; k < HD; k++) {
            float a[4];
#pragma unroll
            for (int ii = 0; ii < 4; ii++) a[ii] = Qs[(ty * 4 + ii) * HD + k];
            float4 bv = *reinterpret_cast<const float4*>(&KT[k * 68 + tx * 4]);
            float bb[4] = {bv.x, bv.y, bv.z, bv.w};
#pragma unroll
            for (int ii = 0; ii < 4; ii++)
#pragma unroll
                for (int jj = 0; jj < 4; jj++)
                    s[ii][jj] += a[ii] * bb[jj];
        }

        // Scale + causal mask + write to shared
#pragma unroll
        for (int ii = 0; ii < 4; ii++) {
            int qi = q0 + ty * 4 + ii;
#pragma unroll
            for (int jj = 0; jj < 4; jj++) {
                int kj = k0 + tx * 4 + jj;
                Sst[(ty * 4 + ii) * 68 + (tx * 4 + jj)] =
                    (kj <= qi) ? s[ii][jj] * scale : -INFINITY;
            }
        }
        __syncthreads();

        // Online softmax update (one thread per row)
        if (tid < 64) {
            const int i = tid;
            float m_old = row_m[i];
            float mt = -INFINITY;
#pragma unroll 8
            for (int j = 0; j < 64; j++) mt = fmaxf(mt, Sst[i * 68 + j]);
            float m_new = fmaxf(m_old, mt);
            float corr = __expf(m_old - m_new);
            float l = row_l[i] * corr;
#pragma unroll 8
            for (int j = 0; j < 64; j++) {
                float p = __expf(Sst[i * 68 + j] - m_new);
                Sst[i * 68 + j] = p;
                l += p;
            }
            row_m[i] = m_new;
            row_l[i] = l;
            row_c[i] = corr;
        }
        __syncthreads();

        // Rescale accumulators, then O += P @ V
        float corr[4];
#pragma unroll
        for (int ii = 0; ii < 4; ii++) corr[ii] = row_c[ty * 4 + ii];
#pragma unroll
        for (int ii = 0; ii < 4; ii++)
#pragma unroll
            for (int jj = 0; jj < 8; jj++) o[ii][jj] *= corr[ii];

        for (int j = 0; j < 64; j++) {
            float p[4];
#pragma unroll
            for (int ii = 0; ii < 4; ii++) p[ii] = Sst[(ty * 4 + ii) * 68 + j];
            float4 v0 = *reinterpret_cast<const float4*>(&Vs[j * HD + tx * 4]);
            float4 v1 = *reinterpret_cast<const float4*>(&Vs[j * HD + 64 + tx * 4]);
            float vv[8] = {v0.x, v0.y, v0.z, v0.w, v1.x, v1.y, v1.z, v1.w};
#pragma unroll
            for (int ii = 0; ii < 4; ii++)
#pragma unroll
                for (int jj = 0; jj < 8; jj++)
                    o[ii][jj] += p[ii] * vv[jj];
        }
    }

    // Normalize and write out: att layout (b, s, h*HD + d)
    float inv_l[4];
#pragma unroll
    for (int ii = 0; ii < 4; ii++) inv_l[ii] = 1.f / row_l[ty * 4 + ii];

    const int obase = (b * SS_ + q0) * DD + h * HD;
#pragma unroll
    for (int ii = 0; ii < 4; ii++) {
        int r = ty * 4 + ii;
        float4 w0, w1;
        w0.x = o[ii][0] * inv_l[ii];
        w0.y = o[ii][1] * inv_l[ii];
        w0.z = o[ii][2] * inv_l[ii];
        w0.w = o[ii][3] * inv_l[ii];
        w1.x = o[ii][4] * inv_l[ii];
        w1.y = o[ii][5] * inv_l[ii];
        w1.z = o[ii][6] * inv_l[ii];
        w1.w = o[ii][7] * inv_l[ii];
        *reinterpret_cast<float4*>(&att[obase + r * DD + tx * 4])      = w0;
        *reinterpret_cast<float4*>(&att[obase + r * DD + 64 + tx * 4]) = w1;
    }
}

// ---------------------------------------------------------------------------
// Launch
// ---------------------------------------------------------------------------
extern "C" void kernel_launch(void* const* d_in, const int* in_sizes, int n_in,
                              void* d_out, int out_size)
{
    const float* x      = (const float*)d_in[0];
    const float* W_qkv  = (const float*)d_in[1];
    const float* b_qkv  = (const float*)d_in[2];
    const float* W_out  = (const float*)d_in[3];
    const float* b_out  = (const float*)d_in[4];
    float* out          = (float*)d_out;

    float *qkv_ptr, *att_ptr;
    cudaGetSymbolAddress((void**)&qkv_ptr, g_qkv);
    cudaGetSymbolAddress((void**)&att_ptr, g_att);

    cudaFuncSetAttribute(flash_attn_kernel,
                         cudaFuncAttributeMaxDynamicSharedMemorySize, ATTN_SMEM_BYTES);

    // QKV projection: [4096,2048] @ [2048,6144]
    sgemm_bias_kernel<<<dim3(N_QKV / 128, M_TOT / 128), 256>>>(
        x, W_qkv, b_qkv, qkv_ptr, M_TOT, N_QKV, DD);

    // Fused causal attention
    flash_attn_kernel<<<dim3(SS_ / 64, HH, BB), 256, ATTN_SMEM_BYTES>>>(qkv_ptr, att_ptr);

    // Output projection: [4096,2048] @ [2048,2048]
    sgemm_bias_kernel<<<dim3(DD / 128, M_TOT / 128), 256>>>(
        att_ptr, W_out, b_out, out, M_TOT, DD, DD);
}

// round 3
// speedup vs baseline: 1.4965x; 1.4965x over previous
#include <cuda_runtime.h>
#include <math.h>
#include <stdint.h>

#define BB 2
#define SS_ 2048
#define DD 2048
#define HH 16
#define HD 128
#define M_TOT (BB * SS_)     // 4096
#define N_QKV (3 * DD)       // 6144

__device__ float g_qkv[M_TOT * N_QKV];   // (b*s, 3*d)
__device__ float g_att[M_TOT * DD];      // (b, s, d)

// ---------------------------------------------------------------------------
// TF32 tensor-core GEMM: C[M,N] = A[M,K] @ B[K,N] + bias
// BM=BN=128, BK=32, 256 threads (8 warps as 2m x 4n), warp tile 64x32.
// mma.sync.m16n8k8.tf32, rna-rounded operands, fp32 accumulate.
// Smem XOR-swizzled (16B granule): conflict-free STS.128 and fragment LDS.
// ---------------------------------------------------------------------------
#define GBM 128
#define GBN 128
#define GBK 32
#define GEMM_SMEM_BYTES ((2 * GBM * GBK + 2 * GBK * GBN) * 4)   // 64 KB

__device__ __forceinline__ uint32_t f2tf(float f) {
    uint32_t u;
    asm("cvt.rna.tf32.f32 %0, %1;" : "=r"(u) : "f"(f));
    return u;
}

__device__ __forceinline__ void mma_tf32(float* d, const uint32_t* a, const uint32_t* b) {
    asm volatile(
        "mma.sync.aligned.m16n8k8.row.col.f32.tf32.tf32.f32 "
        "{%0,%1,%2,%3}, {%4,%5,%6,%7}, {%8,%9}, {%0,%1,%2,%3};\n"
        : "+f"(d[0]), "+f"(d[1]), "+f"(d[2]), "+f"(d[3])
        : "r"(a[0]), "r"(a[1]), "r"(a[2]), "r"(a[3]), "r"(b[0]), "r"(b[1]));
}

__global__ __launch_bounds__(256) void gemm_tf32_kernel(
    const float* __restrict__ A, const float* __restrict__ Bm,
    const float* __restrict__ bias, float* __restrict__ C,
    int M, int N, int K)
{
    extern __shared__ uint32_t sh[];
    uint32_t* As = sh;                    // [2][128][32]  swizzled
    uint32_t* Bs = sh + 2 * GBM * GBK;    // [2][32][128]  swizzled

    const int tid  = threadIdx.x;
    const int lane = tid & 31;
    const int wid  = tid >> 5;
    const int wm   = wid & 1;   // 0..1  (64 rows each)
    const int wn   = wid >> 1;  // 0..3  (32 cols each)
    const int g    = lane >> 2; // 0..7
    const int c    = lane & 3;  // 0..3

    const int m0 = blockIdx.y * GBM;
    const int n0 = blockIdx.x * GBN;

    float acc[4][4][4];
#pragma unroll
    for (int i = 0; i < 4; i++)
#pragma unroll
        for (int j = 0; j < 4; j++)
#pragma unroll
            for (int l = 0; l < 4; l++) acc[i][j][l] = 0.f;

    float4 ra[4], rb[4];

    // ---- global loads into registers ----
    auto ldg = [&](int k0) {
#pragma unroll
        for (int l = 0; l < 4; l++) {
            int idx = l * 256 + tid;
            int mm = idx >> 3, kc = (idx & 7) << 2;
            ra[l] = *reinterpret_cast<const float4*>(&A[(size_t)(m0 + mm) * K + k0 + kc]);
        }
#pragma unroll
        for (int l = 0; l < 4; l++) {
            int idx = l * 256 + tid;
            int kk = idx >> 5, nc = (idx & 31) << 2;
            rb[l] = *reinterpret_cast<const float4*>(&Bm[(size_t)(k0 + kk) * N + n0 + nc]);
        }
    };

    // ---- register -> smem (with rna tf32 rounding, XOR swizzle) ----
    auto sts = [&](int s) {
        uint32_t* as = As + s * GBM * GBK;
        uint32_t* bs = Bs + s * GBK * GBN;
#pragma unroll
        for (int l = 0; l < 4; l++) {
            int idx = l * 256 + tid;
            int mm = idx >> 3, kslot = idx & 7;
            int slot = kslot ^ (mm & 7);
            uint4 u = make_uint4(f2tf(ra[l].x), f2tf(ra[l].y), f2tf(ra[l].z), f2tf(ra[l].w));
            *reinterpret_cast<uint4*>(&as[mm * GBK + slot * 4]) = u;
        }
#pragma unroll
        for (int l = 0; l < 4; l++) {
            int idx = l * 256 + tid;
            int kk = idx >> 5, nslot = idx & 31;
            int slot = nslot ^ (kk & 7);
            uint4 u = make_uint4(f2tf(rb[l].x), f2tf(rb[l].y), f2tf(rb[l].z), f2tf(rb[l].w));
            *reinterpret_cast<uint4*>(&bs[kk * GBN + slot * 4]) = u;
        }
    };

    // ---- compute one 32-deep K slab from stage s ----
    auto compute = [&](int s) {
        const uint32_t* as = As + s * GBM * GBK;
        const uint32_t* bs = Bs + s * GBK * GBN;
#pragma unroll
        for (int ks = 0; ks < 4; ks++) {
            uint32_t af[4][4], bf[4][2];
#pragma unroll
            for (int mf = 0; mf < 4; mf++) {
                int m = wm * 64 + mf * 16 + g;       // m % 8 == g
                int s0 = (ks * 2) ^ g;
                int s1 = (ks * 2 + 1) ^ g;
                af[mf][0] = as[m * GBK + s0 * 4 + c];
                af[mf][1] = as[(m + 8) * GBK + s0 * 4 + c];
                af[mf][2] = as[m * GBK + s1 * 4 + c];
                af[mf][3] = as[(m + 8) * GBK + s1 * 4 + c];
            }
#pragma unroll
            for (int nf = 0; nf < 4; nf++) {
                int k1 = ks * 8 + c;
                int k2 = k1 + 4;
                int n4 = wn * 8 + nf * 2 + (g >> 2); // (n / 4)
                int nj = g & 3;                      // (n % 4)
                bf[nf][0] = bs[k1 * GBN + ((n4 ^ (k1 & 7)) << 2) + nj];
                bf[nf][1] = bs[k2 * GBN + ((n4 ^ (k2 & 7)) << 2) + nj];
            }
#pragma unroll
            for (int mf = 0; mf < 4; mf++)
#pragma unroll
                for (int nf = 0; nf < 4; nf++)
                    mma_tf32(acc[mf][nf], af[mf], bf[nf]);
        }
    };

    const int niter = K / GBK;
    ldg(0);
    sts(0);
    __syncthreads();

    for (int it = 0; it < niter; it++) {
        int s = it & 1;
        if (it + 1 < niter) ldg((it + 1) * GBK);
        compute(s);
        if (it + 1 < niter) {
            sts(s ^ 1);
            __syncthreads();
        }
    }

    // ---- epilogue: acc + bias -> C ----
#pragma unroll
    for (int mf = 0; mf < 4; mf++) {
        int r = m0 + wm * 64 + mf * 16 + g;
#pragma unroll
        for (int nf = 0; nf < 4; nf++) {
            int col = n0 + wn * 32 + nf * 8 + c * 2;
            float b0v = bias[col], b1v = bias[col + 1];
            *reinterpret_cast<float2*>(&C[(size_t)r * N + col]) =
                make_float2(acc[mf][nf][0] + b0v, acc[mf][nf][1] + b1v);
            *reinterpret_cast<float2*>(&C[(size_t)(r + 8) * N + col]) =
                make_float2(acc[mf][nf][2] + b0v, acc[mf][nf][3] + b1v);
        }
    }
}

// ---------------------------------------------------------------------------
// Flash attention (fp32, online softmax, causal) — unchanged from R1.
// ---------------------------------------------------------------------------
#define ATTN_SMEM_FLOATS (64 * 128 + 128 * 68 + 64 * 128 + 64 * 68 + 192)
#define ATTN_SMEM_BYTES  (ATTN_SMEM_FLOATS * 4)

__global__ __launch_bounds__(256) void flash_attn_kernel(
    const float* __restrict__ qkv, float* __restrict__ att)
{
    extern __shared__ float sm[];
    float* Qs    = sm;                      // [64][128]
    float* KT    = Qs + 64 * 128;           // [128][68]
    float* Vs    = KT + 128 * 68;           // [64][128]
    float* Sst   = Vs + 64 * 128;           // [64][68]
    float* row_m = Sst + 64 * 68;
    float* row_l = row_m + 64;
    float* row_c = row_l + 64;

    const int tid = threadIdx.x;
    const int tx = tid & 15;
    const int ty = tid >> 4;
    const int qb = blockIdx.x;
    const int h  = blockIdx.y;
    const int b  = blockIdx.z;
    const int q0 = qb * 64;
    const float scale = 0.08838834764831845f;

    const int base = b * SS_ * N_QKV + h * HD;

#pragma unroll
    for (int l = 0; l < 8; l++) {
        int idx = tid + l * 256;
        int i   = idx >> 5;
        int d4  = (idx & 31) << 2;
        float4 v = *reinterpret_cast<const float4*>(&qkv[base + (q0 + i) * N_QKV + d4]);
        *reinterpret_cast<float4*>(&Qs[i * HD + d4]) = v;
    }
    if (tid < 64) { row_m[tid] = -INFINITY; row_l[tid] = 0.f; }

    float o[4][8];
#pragma unroll
    for (int ii = 0; ii < 4; ii++)
#pragma unroll
        for (int jj = 0; jj < 8; jj++) o[ii][jj] = 0.f;

    for (int kb = 0; kb <= qb; kb++) {
        __syncthreads();
        const int k0 = kb * 64;

#pragma unroll
        for (int l = 0; l < 8; l++) {
            int idx = tid + l * 256;
            int j   = idx >> 5;
            int d4  = (idx & 31) << 2;
            const float* src = &qkv[base + (k0 + j) * N_QKV];
            float4 kv = *reinterpret_cast<const float4*>(&src[DD + d4]);
            KT[(d4 + 0) * 68 + j] = kv.x;
            KT[(d4 + 1) * 68 + j] = kv.y;
            KT[(d4 + 2) * 68 + j] = kv.z;
            KT[(d4 + 3) * 68 + j] = kv.w;
            float4 vv = *reinterpret_cast<const float4*>(&src[2 * DD + d4]);
            *reinterpret_cast<float4*>(&Vs[j * HD + d4]) = vv;
        }
        __syncthreads();

        float s[4][4];
#pragma unroll
        for (int ii = 0; ii < 4; ii++)
#pragma unroll
            for (int jj = 0; jj < 4; jj++) s[ii][jj] = 0.f;

        for (int k = 0; k < HD; k++) {
            float a[4];
#pragma unroll
            for (int ii = 0; ii < 4; ii++) a[ii] = Qs[(ty * 4 + ii) * HD + k];
            float4 bv = *reinterpret_cast<const float4*>(&KT[k * 68 + tx * 4]);
            float bb[4] = {bv.x, bv.y, bv.z, bv.w};
#pragma unroll
            for (int ii = 0; ii < 4; ii++)
#pragma unroll
                for (int jj = 0; jj < 4; jj++)
                    s[ii][jj] += a[ii] * bb[jj];
        }

#pragma unroll
        for (int ii = 0; ii < 4; ii++) {
            int qi = q0 + ty * 4 + ii;
#pragma unroll
            for (int jj = 0; jj < 4; jj++) {
                int kj = k0 + tx * 4 + jj;
                Sst[(ty * 4 + ii) * 68 + (tx * 4 + jj)] =
                    (kj <= qi) ? s[ii][jj] * scale : -INFINITY;
            }
        }
        __syncthreads();

        if (tid < 64) {
            const int i = tid;
            float m_old = row_m[i];
            float mt = -INFINITY;
#pragma unroll 8
            for (int j = 0; j < 64; j++) mt = fmaxf(mt, Sst[i * 68 + j]);
            float m_new = fmaxf(m_old, mt);
            float corr = __expf(m_old - m_new);
            float l = row_l[i] * corr;
#pragma unroll 8
            for (int j = 0; j < 64; j++) {
                float p = __expf(Sst[i * 68 + j] - m_new);
                Sst[i * 68 + j] = p;
                l += p;
            }
            row_m[i] = m_new;
            row_l[i] = l;
            row_c[i] = corr;
        }
        __syncthreads();

        float corr[4];
#pragma unroll
        for (int ii = 0; ii < 4; ii++) corr[ii] = row_c[ty * 4 + ii];
#pragma unroll
        for (int ii = 0; ii < 4; ii++)
#pragma unroll
            for (int jj = 0; jj < 8; jj++) o[ii][jj] *= corr[ii];

        for (int j = 0; j < 64; j++) {
            float p[4];
#pragma unroll
            for (int ii = 0; ii < 4; ii++) p[ii] = Sst[(ty * 4 + ii) * 68 + j];
            float4 v0 = *reinterpret_cast<const float4*>(&Vs[j * HD + tx * 4]);
            float4 v1 = *reinterpret_cast<const float4*>(&Vs[j * HD + 64 + tx * 4]);
            float vv[8] = {v0.x, v0.y, v0.z, v0.w, v1.x, v1.y, v1.z, v1.w};
#pragma unroll
            for (int ii = 0; ii < 4; ii++)
#pragma unroll
                for (int jj = 0; jj < 8; jj++)
                    o[ii][jj] += p[ii] * vv[jj];
        }
    }

    float inv_l[4];
#pragma unroll
    for (int ii = 0; ii < 4; ii++) inv_l[ii] = 1.f / row_l[ty * 4 + ii];

    const int obase = (b * SS_ + q0) * DD + h * HD;
#pragma unroll
    for (int ii = 0; ii < 4; ii++) {
        int r = ty * 4 + ii;
        float4 w0, w1;
        w0.x = o[ii][0] * inv_l[ii];
        w0.y = o[ii][1] * inv_l[ii];
        w0.z = o[ii][2] * inv_l[ii];
        w0.w = o[ii][3] * inv_l[ii];
        w1.x = o[ii][4] * inv_l[ii];
        w1.y = o[ii][5] * inv_l[ii];
        w1.z = o[ii][6] * inv_l[ii];
        w1.w = o[ii][7] * inv_l[ii];
        *reinterpret_cast<float4*>(&att[obase + r * DD + tx * 4])      = w0;
        *reinterpret_cast<float4*>(&att[obase + r * DD + 64 + tx * 4]) = w1;
    }
}

// ---------------------------------------------------------------------------
// Launch
// ---------------------------------------------------------------------------
extern "C" void kernel_launch(void* const* d_in, const int* in_sizes, int n_in,
                              void* d_out, int out_size)
{
    const float* x      = (const float*)d_in[0];
    const float* W_qkv  = (const float*)d_in[1];
    const float* b_qkv  = (const float*)d_in[2];
    const float* W_out  = (const float*)d_in[3];
    const float* b_out  = (const float*)d_in[4];
    float* out          = (float*)d_out;

    float *qkv_ptr, *att_ptr;
    cudaGetSymbolAddress((void**)&qkv_ptr, g_qkv);
    cudaGetSymbolAddress((void**)&att_ptr, g_att);

    cudaFuncSetAttribute(gemm_tf32_kernel,
                         cudaFuncAttributeMaxDynamicSharedMemorySize, GEMM_SMEM_BYTES);
    cudaFuncSetAttribute(flash_attn_kernel,
                         cudaFuncAttributeMaxDynamicSharedMemorySize, ATTN_SMEM_BYTES);

    // QKV projection: [4096,2048] @ [2048,6144]
    gemm_tf32_kernel<<<dim3(N_QKV / GBN, M_TOT / GBM), 256, GEMM_SMEM_BYTES>>>(
        x, W_qkv, b_qkv, qkv_ptr, M_TOT, N_QKV, DD);

    // Fused causal attention
    flash_attn_kernel<<<dim3(SS_ / 64, HH, BB), 256, ATTN_SMEM_BYTES>>>(qkv_ptr, att_ptr);

    // Output projection: [4096,2048] @ [2048,2048]
    gemm_tf32_kernel<<<dim3(DD / GBN, M_TOT / GBM), 256, GEMM_SMEM_BYTES>>>(
        att_ptr, W_out, b_out, out, M_TOT, DD, DD);
}

// round 4
// speedup vs baseline: 2.7973x; 1.8692x over previous
#include <cuda_runtime.h>
#include <math.h>
#include <stdint.h>

#define BB 2
#define SS_ 2048
#define DD 2048
#define HH 16
#define HD 128
#define M_TOT (BB * SS_)     // 4096
#define N_QKV (3 * DD)       // 6144

__device__ float g_qkv[M_TOT * N_QKV];   // (b*s, 3*d)
__device__ float g_att[M_TOT * DD];      // (b, s, d)

// ===========================================================================
// TF32 tensor-core GEMM (unchanged from R2 — known good)
// ===========================================================================
#define GBM 128
#define GBN 128
#define GBK 32
#define GEMM_SMEM_BYTES ((2 * GBM * GBK + 2 * GBK * GBN) * 4)   // 64 KB

__device__ __forceinline__ uint32_t f2tf(float f) {
    uint32_t u;
    asm("cvt.rna.tf32.f32 %0, %1;" : "=r"(u) : "f"(f));
    return u;
}

__device__ __forceinline__ void mma_tf32(float* d, const uint32_t* a, const uint32_t* b) {
    asm volatile(
        "mma.sync.aligned.m16n8k8.row.col.f32.tf32.tf32.f32 "
        "{%0,%1,%2,%3}, {%4,%5,%6,%7}, {%8,%9}, {%0,%1,%2,%3};\n"
        : "+f"(d[0]), "+f"(d[1]), "+f"(d[2]), "+f"(d[3])
        : "r"(a[0]), "r"(a[1]), "r"(a[2]), "r"(a[3]), "r"(b[0]), "r"(b[1]));
}

__global__ __launch_bounds__(256) void gemm_tf32_kernel(
    const float* __restrict__ A, const float* __restrict__ Bm,
    const float* __restrict__ bias, float* __restrict__ C,
    int M, int N, int K)
{
    extern __shared__ uint32_t sh[];
    uint32_t* As = sh;
    uint32_t* Bs = sh + 2 * GBM * GBK;

    const int tid  = threadIdx.x;
    const int lane = tid & 31;
    const int wid  = tid >> 5;
    const int wm   = wid & 1;
    const int wn   = wid >> 1;
    const int g    = lane >> 2;
    const int c    = lane & 3;

    const int m0 = blockIdx.y * GBM;
    const int n0 = blockIdx.x * GBN;

    float acc[4][4][4];
#pragma unroll
    for (int i = 0; i < 4; i++)
#pragma unroll
        for (int j = 0; j < 4; j++)
#pragma unroll
            for (int l = 0; l < 4; l++) acc[i][j][l] = 0.f;

    float4 ra[4], rb[4];

    auto ldg = [&](int k0) {
#pragma unroll
        for (int l = 0; l < 4; l++) {
            int idx = l * 256 + tid;
            int mm = idx >> 3, kc = (idx & 7) << 2;
            ra[l] = *reinterpret_cast<const float4*>(&A[(size_t)(m0 + mm) * K + k0 + kc]);
        }
#pragma unroll
        for (int l = 0; l < 4; l++) {
            int idx = l * 256 + tid;
            int kk = idx >> 5, nc = (idx & 31) << 2;
            rb[l] = *reinterpret_cast<const float4*>(&Bm[(size_t)(k0 + kk) * N + n0 + nc]);
        }
    };

    auto sts = [&](int s) {
        uint32_t* as = As + s * GBM * GBK;
        uint32_t* bs = Bs + s * GBK * GBN;
#pragma unroll
        for (int l = 0; l < 4; l++) {
            int idx = l * 256 + tid;
            int mm = idx >> 3, kslot = idx & 7;
            int slot = kslot ^ (mm & 7);
            uint4 u = make_uint4(f2tf(ra[l].x), f2tf(ra[l].y), f2tf(ra[l].z), f2tf(ra[l].w));
            *reinterpret_cast<uint4*>(&as[mm * GBK + slot * 4]) = u;
        }
#pragma unroll
        for (int l = 0; l < 4; l++) {
            int idx = l * 256 + tid;
            int kk = idx >> 5, nslot = idx & 31;
            int slot = nslot ^ (kk & 7);
            uint4 u = make_uint4(f2tf(rb[l].x), f2tf(rb[l].y), f2tf(rb[l].z), f2tf(rb[l].w));
            *reinterpret_cast<uint4*>(&bs[kk * GBN + slot * 4]) = u;
        }
    };

    auto compute = [&](int s) {
        const uint32_t* as = As + s * GBM * GBK;
        const uint32_t* bs = Bs + s * GBK * GBN;
#pragma unroll
        for (int ks = 0; ks < 4; ks++) {
            uint32_t af[4][4], bf[4][2];
#pragma unroll
            for (int mf = 0; mf < 4; mf++) {
                int m = wm * 64 + mf * 16 + g;
                int s0 = (ks * 2) ^ g;
                int s1 = (ks * 2 + 1) ^ g;
                af[mf][0] = as[m * GBK + s0 * 4 + c];
                af[mf][1] = as[(m + 8) * GBK + s0 * 4 + c];
                af[mf][2] = as[m * GBK + s1 * 4 + c];
                af[mf][3] = as[(m + 8) * GBK + s1 * 4 + c];
            }
#pragma unroll
            for (int nf = 0; nf < 4; nf++) {
                int k1 = ks * 8 + c;
                int k2 = k1 + 4;
                int n4 = wn * 8 + nf * 2 + (g >> 2);
                int nj = g & 3;
                bf[nf][0] = bs[k1 * GBN + ((n4 ^ (k1 & 7)) << 2) + nj];
                bf[nf][1] = bs[k2 * GBN + ((n4 ^ (k2 & 7)) << 2) + nj];
            }
#pragma unroll
            for (int mf = 0; mf < 4; mf++)
#pragma unroll
                for (int nf = 0; nf < 4; nf++)
                    mma_tf32(acc[mf][nf], af[mf], bf[nf]);
        }
    };

    const int niter = K / GBK;
    ldg(0);
    sts(0);
    __syncthreads();

    for (int it = 0; it < niter; it++) {
        int s = it & 1;
        if (it + 1 < niter) ldg((it + 1) * GBK);
        compute(s);
        if (it + 1 < niter) {
            sts(s ^ 1);
            __syncthreads();
        }
    }

#pragma unroll
    for (int mf = 0; mf < 4; mf++) {
        int r = m0 + wm * 64 + mf * 16 + g;
#pragma unroll
        for (int nf = 0; nf < 4; nf++) {
            int col = n0 + wn * 32 + nf * 8 + c * 2;
            float b0v = bias[col], b1v = bias[col + 1];
            *reinterpret_cast<float2*>(&C[(size_t)r * N + col]) =
                make_float2(acc[mf][nf][0] + b0v, acc[mf][nf][1] + b1v);
            *reinterpret_cast<float2*>(&C[(size_t)(r + 8) * N + col]) =
                make_float2(acc[mf][nf][2] + b0v, acc[mf][nf][3] + b1v);
        }
    }
}

// ===========================================================================
// Tensor-core flash attention (tf32 mma, causal, cp.async pipelined)
// CTA: 128 queries, 8 warps x 16 rows. 64-key tiles over HD=128.
// ===========================================================================
#define AT_BM 128
#define AT_BN 64
#define KSTR 132            // K smem row stride (4 mod 32 -> conflict-free B-frag reads)
#define VSTR 136            // V smem row stride (8 mod 32)
#define PSTR 68

// smem layout (in floats)
#define SM_QF 0                               // 8 rowblk * 16 ks * 32 lane * 4 = 16384
#define SM_K0 16384                           // 64*132 = 8448
#define SM_K1 (16384 + 8448)
#define SM_V  (16384 + 16896)                 // 64*136 = 8704
#define SM_P  (16384 + 16896 + 8704)          // 8 warps * 16*68 = 8704
#define AT_SMEM_FLOATS (16384 + 16896 + 8704 + 8704)
#define AT_SMEM_BYTES  (AT_SMEM_FLOATS * 4)   // 202752 B

__device__ __forceinline__ void cp16(uint32_t saddr, const float* gptr) {
    asm volatile("cp.async.cg.shared.global [%0], [%1], 16;" :: "r"(saddr), "l"(gptr));
}

__global__ __launch_bounds__(256) void flash_attn_tc_kernel(
    const float* __restrict__ qkv, float* __restrict__ att)
{
    extern __shared__ float sm[];
    const int tid  = threadIdx.x;
    const int lane = tid & 31;
    const int w    = tid >> 5;
    const int g    = lane >> 2;
    const int c    = lane & 3;
    const int qb   = (int)gridDim.x - 1 - (int)blockIdx.x;  // long CTAs first
    const int h    = blockIdx.y;
    const int b    = blockIdx.z;
    const int q0   = qb * AT_BM;
    const size_t base = (size_t)b * SS_ * N_QKV + (size_t)h * HD;
    const float scale = 0.08838834764831845f;  // 1/sqrt(128)

    uint32_t smb;
    asm("{ .reg .u64 t; cvta.to.shared.u64 t, %1; cvt.u32.u64 %0, t; }" : "=r"(smb) : "l"(sm));

    // ---- stage Q -> tf32 fragment-major smem (with scale folded in) ----
#pragma unroll
    for (int i = 0; i < 16; i++) {
        int id = tid + i * 256;            // float4 index over 128x128
        int r  = id >> 5;
        int c4 = (id & 31) << 2;
        float4 v = *reinterpret_cast<const float4*>(&qkv[base + (size_t)(q0 + r) * N_QKV + c4]);
        int rb = r >> 4, rr = r & 15, gg = rr & 7, half = rr >> 3;
        int ks = c4 >> 3, khalf = (c4 >> 2) & 1;
        int reg = half + 2 * khalf;
        int ba = ((rb * 16 + ks) * 32) * 4 + reg;
        float vv[4] = {v.x, v.y, v.z, v.w};
#pragma unroll
        for (int j = 0; j < 4; j++)
            sm[SM_QF + ba + (gg * 4 + j) * 4] = __uint_as_float(f2tf(vv[j] * scale));
    }

    float o[16][4];
#pragma unroll
    for (int nt = 0; nt < 16; nt++)
#pragma unroll
        for (int l = 0; l < 4; l++) o[nt][l] = 0.f;
    float m0 = -INFINITY, m1 = -INFINITY, l0 = 0.f, l1 = 0.f;

    const int r0 = q0 + w * 16 + g;
    const int nkb = 2 * qb + 2;
    const uint32_t pbase = SM_P + w * (16 * PSTR);

    // prologue: K(0) -> stage 0
#pragma unroll
    for (int i = 0; i < 8; i++) {
        int id = tid + i * 256;
        int row = id >> 5, c16 = (id & 31) << 2;
        cp16(smb + (uint32_t)(SM_K0 + row * KSTR + c16) * 4,
             &qkv[base + (size_t)row * N_QKV + DD + c16]);
    }
    asm volatile("cp.async.commit_group;");

    for (int kb = 0; kb < nkb; kb++) {
        const int k0 = kb * AT_BN;
        const int sK = (kb & 1) ? SM_K1 : SM_K0;

        // issue V(kb)
#pragma unroll
        for (int i = 0; i < 8; i++) {
            int id = tid + i * 256;
            int row = id >> 5, c16 = (id & 31) << 2;
            cp16(smb + (uint32_t)(SM_V + row * VSTR + c16) * 4,
                 &qkv[base + (size_t)(k0 + row) * N_QKV + 2 * DD + c16]);
        }
        asm volatile("cp.async.commit_group;");
        asm volatile("cp.async.wait_group 1;");   // K(kb) ready
        __syncthreads();

        // ---- S = Q K^T ----
        float s[8][4];
#pragma unroll
        for (int nt = 0; nt < 8; nt++)
#pragma unroll
            for (int l = 0; l < 4; l++) s[nt][l] = 0.f;

#pragma unroll
        for (int ks = 0; ks < 16; ks++) {
            float4 qa = *reinterpret_cast<const float4*>(&sm[SM_QF + ((w * 16 + ks) * 32 + lane) * 4]);
            uint32_t a[4] = {__float_as_uint(qa.x), __float_as_uint(qa.y),
                             __float_as_uint(qa.z), __float_as_uint(qa.w)};
#pragma unroll
            for (int nt = 0; nt < 8; nt++) {
                const float* kp = &sm[sK + (nt * 8 + g) * KSTR + ks * 8 + c];
                uint32_t bfr[2] = {f2tf(kp[0]), f2tf(kp[4])};
                mma_tf32(s[nt], a, bfr);
            }
        }

        // issue K(kb+1) into other stage (empty commit on last iter)
        if (kb + 1 < nkb) {
            const int sKn = (kb & 1) ? SM_K0 : SM_K1;
            const int k0n = (kb + 1) * AT_BN;
#pragma unroll
            for (int i = 0; i < 8; i++) {
                int id = tid + i * 256;
                int row = id >> 5, c16 = (id & 31) << 2;
                cp16(smb + (uint32_t)(sKn + row * KSTR + c16) * 4,
                     &qkv[base + (size_t)(k0n + row) * N_QKV + DD + c16]);
            }
        }
        asm volatile("cp.async.commit_group;");

        // ---- causal mask (warp-uniform skip for interior tiles) ----
        if (k0 + 63 > q0 + w * 16) {
#pragma unroll
            for (int nt = 0; nt < 8; nt++) {
                int col = k0 + nt * 8 + 2 * c;
                if (col     > r0)     s[nt][0] = -INFINITY;
                if (col + 1 > r0)     s[nt][1] = -INFINITY;
                if (col     > r0 + 8) s[nt][2] = -INFINITY;
                if (col + 1 > r0 + 8) s[nt][3] = -INFINITY;
            }
        }

        // ---- online softmax (rows g and g+8) ----
        float mt0 = -INFINITY, mt1 = -INFINITY;
#pragma unroll
        for (int nt = 0; nt < 8; nt++) {
            mt0 = fmaxf(mt0, fmaxf(s[nt][0], s[nt][1]));
            mt1 = fmaxf(mt1, fmaxf(s[nt][2], s[nt][3]));
        }
        mt0 = fmaxf(mt0, __shfl_xor_sync(0xffffffffu, mt0, 1));
        mt0 = fmaxf(mt0, __shfl_xor_sync(0xffffffffu, mt0, 2));
        mt1 = fmaxf(mt1, __shfl_xor_sync(0xffffffffu, mt1, 1));
        mt1 = fmaxf(mt1, __shfl_xor_sync(0xffffffffu, mt1, 2));

        float mn0 = fmaxf(m0, mt0), mn1 = fmaxf(m1, mt1);
        float cr0 = __expf(m0 - mn0), cr1 = __expf(m1 - mn1);
        m0 = mn0; m1 = mn1;

        float ps0 = 0.f, ps1 = 0.f;
#pragma unroll
        for (int nt = 0; nt < 8; nt++) {
            float p00 = __expf(s[nt][0] - m0);
            float p01 = __expf(s[nt][1] - m0);
            float p10 = __expf(s[nt][2] - m1);
            float p11 = __expf(s[nt][3] - m1);
            ps0 += p00 + p01;
            ps1 += p10 + p11;
            // store P as tf32 (A-operand for PV)
            uint2 u0 = make_uint2(f2tf(p00), f2tf(p01));
            uint2 u1 = make_uint2(f2tf(p10), f2tf(p11));
            *reinterpret_cast<uint2*>(&sm[pbase + g * PSTR + nt * 8 + 2 * c])       = u0;
            *reinterpret_cast<uint2*>(&sm[pbase + (g + 8) * PSTR + nt * 8 + 2 * c]) = u1;
        }
        ps0 += __shfl_xor_sync(0xffffffffu, ps0, 1);
        ps0 += __shfl_xor_sync(0xffffffffu, ps0, 2);
        ps1 += __shfl_xor_sync(0xffffffffu, ps1, 1);
        ps1 += __shfl_xor_sync(0xffffffffu, ps1, 2);
        l0 = l0 * cr0 + ps0;
        l1 = l1 * cr1 + ps1;

        // rescale O
#pragma unroll
        for (int nt = 0; nt < 16; nt++) {
            o[nt][0] *= cr0; o[nt][1] *= cr0;
            o[nt][2] *= cr1; o[nt][3] *= cr1;
        }

        asm volatile("cp.async.wait_group 1;");   // V(kb) ready
        __syncthreads();                          // also orders P stores

        // ---- O += P V ----  (V used raw fp32 -> tf32 truncation)
#pragma unroll
        for (int ks2 = 0; ks2 < 8; ks2++) {
            uint32_t a[4];
            a[0] = __float_as_uint(sm[pbase + g * PSTR + ks2 * 8 + c]);
            a[1] = __float_as_uint(sm[pbase + (g + 8) * PSTR + ks2 * 8 + c]);
            a[2] = __float_as_uint(sm[pbase + g * PSTR + ks2 * 8 + c + 4]);
            a[3] = __float_as_uint(sm[pbase + (g + 8) * PSTR + ks2 * 8 + c + 4]);
#pragma unroll
            for (int nt = 0; nt < 16; nt++) {
                uint32_t bfr[2] = {
                    __float_as_uint(sm[SM_V + (ks2 * 8 + c) * VSTR + nt * 8 + g]),
                    __float_as_uint(sm[SM_V + (ks2 * 8 + c + 4) * VSTR + nt * 8 + g])};
                mma_tf32(o[nt], a, bfr);
            }
        }
        __syncthreads();   // all warps done with K stage + V before overwrite
    }

    // ---- epilogue ----
    float il0 = 1.f / l0, il1 = 1.f / l1;
    size_t ob = ((size_t)(b * SS_) + q0 + w * 16) * DD + (size_t)h * HD;
#pragma unroll
    for (int nt = 0; nt < 16; nt++) {
        int col = nt * 8 + 2 * c;
        *reinterpret_cast<float2*>(&att[ob + (size_t)g * DD + col]) =
            make_float2(o[nt][0] * il0, o[nt][1] * il0);
        *reinterpret_cast<float2*>(&att[ob + (size_t)(g + 8) * DD + col]) =
            make_float2(o[nt][2] * il1, o[nt][3] * il1);
    }
}

// ===========================================================================
// Launch
// ===========================================================================
extern "C" void kernel_launch(void* const* d_in, const int* in_sizes, int n_in,
                              void* d_out, int out_size)
{
    const float* x      = (const float*)d_in[0];
    const float* W_qkv  = (const float*)d_in[1];
    const float* b_qkv  = (const float*)d_in[2];
    const float* W_out  = (const float*)d_in[3];
    const float* b_out  = (const float*)d_in[4];
    float* out          = (float*)d_out;

    float *qkv_ptr, *att_ptr;
    cudaGetSymbolAddress((void**)&qkv_ptr, g_qkv);
    cudaGetSymbolAddress((void**)&att_ptr, g_att);

    cudaFuncSetAttribute(gemm_tf32_kernel,
                         cudaFuncAttributeMaxDynamicSharedMemorySize, GEMM_SMEM_BYTES);
    cudaFuncSetAttribute(flash_attn_tc_kernel,
                         cudaFuncAttributeMaxDynamicSharedMemorySize, AT_SMEM_BYTES);

    // QKV projection: [4096,2048] @ [2048,6144]
    gemm_tf32_kernel<<<dim3(N_QKV / GBN, M_TOT / GBM), 256, GEMM_SMEM_BYTES>>>(
        x, W_qkv, b_qkv, qkv_ptr, M_TOT, N_QKV, DD);

    // Fused causal attention (tensor-core)
    flash_attn_tc_kernel<<<dim3(SS_ / AT_BM, HH, BB), 256, AT_SMEM_BYTES>>>(qkv_ptr, att_ptr);

    // Output projection: [4096,2048] @ [2048,2048]
    gemm_tf32_kernel<<<dim3(DD / GBN, M_TOT / GBM), 256, GEMM_SMEM_BYTES>>>(
        att_ptr, W_out, b_out, out, M_TOT, DD, DD);
}

// round 9
// speedup vs baseline: 3.3476x; 1.1967x over previous
#include <cuda_runtime.h>
#include <math.h>
#include <stdint.h>

#define BB 2
#define SS_ 2048
#define DD 2048
#define HH 16
#define HD 128
#define M_TOT (BB * SS_)     // 4096
#define N_QKV (3 * DD)       // 6144

__device__ float g_qkv[M_TOT * N_QKV];   // (b*s, 3*d) raw fp32 qkv
__device__ float g_att[M_TOT * DD];      // (b, s, d) attention out (tf32-rounded)
__device__ float g_x [M_TOT * DD];       // x rounded to tf32
__device__ float g_w1[DD * N_QKV];       // W_qkv rounded to tf32
__device__ float g_w2[DD * DD];          // W_out rounded to tf32

__device__ __forceinline__ uint32_t f2tf(float f) {
    uint32_t u;
    asm("cvt.rna.tf32.f32 %0, %1;" : "=r"(u) : "f"(f));
    return u;
}

__device__ __forceinline__ void mma_tf32(float* d, const uint32_t* a, const uint32_t* b) {
    asm volatile(
        "mma.sync.aligned.m16n8k8.row.col.f32.tf32.tf32.f32 "
        "{%0,%1,%2,%3}, {%4,%5,%6,%7}, {%8,%9}, {%0,%1,%2,%3};\n"
        : "+f"(d[0]), "+f"(d[1]), "+f"(d[2]), "+f"(d[3])
        : "r"(a[0]), "r"(a[1]), "r"(a[2]), "r"(a[3]), "r"(b[0]), "r"(b[1]));
}

// ---------------------------------------------------------------------------
// Prep: elementwise rna round fp32 -> tf32 bits (stored as float)
// ---------------------------------------------------------------------------
__global__ __launch_bounds__(256) void cvt_tf32_kernel(
    const float* __restrict__ src, float* __restrict__ dst, int n4)
{
    int stride = gridDim.x * blockDim.x;
    for (int i = blockIdx.x * blockDim.x + threadIdx.x; i < n4; i += stride) {
        float4 v = reinterpret_cast<const float4*>(src)[i];
        uint4 u = make_uint4(f2tf(v.x), f2tf(v.y), f2tf(v.z), f2tf(v.w));
        reinterpret_cast<uint4*>(dst)[i] = u;
    }
}

// ===========================================================================
// TF32 mma.sync GEMM, fragment-major smem staging, no cvt in hot loop.
// Inputs pre-rounded to tf32. BM=BN=128, BK=32, 8 warps (2m x 4n),
// warp tile 64x32.  A frags: [8 mfblk][4 ks] x 132 floats (LDS.128 consume).
// B frags: [4 ks][16 n8] x 66 floats (LDS.64 consume).
// NOTE: no minBlocksPerMultiprocessor — regs must stay unconstrained (R8
// post-mortem: forcing 2 CTAs/SM spilled the accumulator and timed out).
// ===========================================================================
#define GBM 128
#define GBN 128
#define GBK 32
#define AFRAG_FLOATS 4224                 // 32 frags * 132
#define BFRAG_FLOATS 4224                 // 64 frags * 66
#define STAGE_FLOATS (AFRAG_FLOATS + BFRAG_FLOATS)
#define GEMM_SMEM_BYTES (2 * STAGE_FLOATS * 4)   // 67584

__global__ __launch_bounds__(256) void gemm_tf32_kernel(
    const float* __restrict__ A, const float* __restrict__ W,
    const float* __restrict__ bias, float* __restrict__ C,
    int M, int N, int K)
{
    extern __shared__ float sh[];

    const int tid  = threadIdx.x;
    const int lane = tid & 31;
    const int wid  = tid >> 5;
    const int wm   = wid & 1;
    const int wn   = wid >> 1;
    const int g    = lane >> 2;
    const int c    = lane & 3;

    const int m0 = blockIdx.y * GBM;
    const int n0 = blockIdx.x * GBN;

    // A staging: thread covers rows (tid>>3)+32p, k = 4*(tid&7)+j
    const int a_row = tid >> 3;
    const int ak4   = tid & 7;
    const int a_ks  = ak4 >> 1;
    const int a_rh  = 2 * (ak4 & 1);
    // B staging: thread covers k = (tid>>5)*4+p, n = 4*(tid&31)+j
    const int b_n4  = tid & 31;
    const int b_kb  = tid >> 5;
    const int b_n8  = b_n4 >> 1;
    const int b_nl  = (b_n4 & 1) * 32;

    float acc[4][4][4];
#pragma unroll
    for (int i = 0; i < 4; i++)
#pragma unroll
        for (int j = 0; j < 4; j++)
#pragma unroll
            for (int l = 0; l < 4; l++) acc[i][j][l] = 0.f;

    float4 ra[4], rb[4];

    auto ldgA = [&](int k0) {
#pragma unroll
        for (int p = 0; p < 4; p++)
            ra[p] = *reinterpret_cast<const float4*>(
                &A[(size_t)(m0 + a_row + 32 * p) * K + k0 + ak4 * 4]);
    };
    auto stsA = [&](int s) {
        float* dst = sh + s * STAGE_FLOATS;
#pragma unroll
        for (int p = 0; p < 4; p++) {
            int m  = a_row + 32 * p;
            int mf = m >> 4, r16 = m & 15;
            int basef = (mf * 4 + a_ks) * 132 + (r16 & 7) * 16 + (r16 >> 3) + a_rh;
            dst[basef + 0]  = ra[p].x;
            dst[basef + 4]  = ra[p].y;
            dst[basef + 8]  = ra[p].z;
            dst[basef + 12] = ra[p].w;
        }
    };
    auto ldgB = [&](int k0) {
#pragma unroll
        for (int p = 0; p < 4; p++)
            rb[p] = *reinterpret_cast<const float4*>(
                &W[(size_t)(k0 + b_kb * 4 + p) * N + n0 + b_n4 * 4]);
    };
    auto stsB = [&](int s) {
        float* dst = sh + s * STAGE_FLOATS + AFRAG_FLOATS;
#pragma unroll
        for (int p = 0; p < 4; p++) {
            int k   = b_kb * 4 + p;
            int ks  = k >> 3;
            int k8  = k & 7;
            int basef = (ks * 16 + b_n8) * 66 + b_nl + (k8 & 3) * 2 + (k8 >> 2);
            dst[basef + 0]  = rb[p].x;
            dst[basef + 8]  = rb[p].y;
            dst[basef + 16] = rb[p].z;
            dst[basef + 24] = rb[p].w;
        }
    };
    auto compute = [&](int s, int ks) {
        const float* as_ = sh + s * STAGE_FLOATS;
        const float* bs_ = as_ + AFRAG_FLOATS;
        uint32_t af[4][4], bfr[4][2];
#pragma unroll
        for (int mf = 0; mf < 4; mf++) {
            float4 v = *reinterpret_cast<const float4*>(
                as_ + ((wm * 4 + mf) * 4 + ks) * 132 + lane * 4);
            af[mf][0] = __float_as_uint(v.x);
            af[mf][1] = __float_as_uint(v.y);
            af[mf][2] = __float_as_uint(v.z);
            af[mf][3] = __float_as_uint(v.w);
        }
#pragma unroll
        for (int nf = 0; nf < 4; nf++) {
            float2 v = *reinterpret_cast<const float2*>(
                bs_ + (ks * 16 + wn * 4 + nf) * 66 + lane * 2);
            bfr[nf][0] = __float_as_uint(v.x);
            bfr[nf][1] = __float_as_uint(v.y);
        }
#pragma unroll
        for (int mf = 0; mf < 4; mf++)
#pragma unroll
            for (int nf = 0; nf < 4; nf++)
                mma_tf32(acc[mf][nf], af[mf], bfr[nf]);
    };

    const int niter = K / GBK;

    ldgA(0); stsA(0);
    ldgB(0); stsB(0);
    __syncthreads();

    for (int it = 0; it < niter; it++) {
        const int s = it & 1;
        const bool pre = (it + 1 < niter);
        const int k0n = (it + 1) * GBK;

        if (pre) ldgA(k0n);
        compute(s, 0);
        if (pre) { stsA(s ^ 1); ldgB(k0n); }
        compute(s, 1);
        if (pre) stsB(s ^ 1);
        compute(s, 2);
        compute(s, 3);
        __syncthreads();
    }

    // epilogue: acc + bias -> C
#pragma unroll
    for (int mf = 0; mf < 4; mf++) {
        int r = m0 + wm * 64 + mf * 16 + g;
#pragma unroll
        for (int nf = 0; nf < 4; nf++) {
            int col = n0 + wn * 32 + nf * 8 + c * 2;
            float b0v = bias[col], b1v = bias[col + 1];
            *reinterpret_cast<float2*>(&C[(size_t)r * N + col]) =
                make_float2(acc[mf][nf][0] + b0v, acc[mf][nf][1] + b1v);
            *reinterpret_cast<float2*>(&C[(size_t)(r + 8) * N + col]) =
                make_float2(acc[mf][nf][2] + b0v, acc[mf][nf][3] + b1v);
        }
    }
}

// ===========================================================================
// Tensor-core flash attention (tf32 mma.sync) — R4 (passing), epilogue now
// rounds output to tf32 so the out-projection GEMM can skip conversion.
// ===========================================================================
#define AT_BM 128
#define AT_BN 64
#define KSTR 132
#define VSTR 136
#define PSTR 68
#define SM_QF 0
#define SM_K0 16384
#define SM_K1 (16384 + 8448)
#define SM_V  (16384 + 16896)
#define SM_P  (16384 + 16896 + 8704)
#define AT_SMEM_FLOATS (16384 + 16896 + 8704 + 8704)
#define AT_SMEM_BYTES  (AT_SMEM_FLOATS * 4)

__device__ __forceinline__ void cp16(uint32_t saddr, const float* gptr) {
    asm volatile("cp.async.cg.shared.global [%0], [%1], 16;" :: "r"(saddr), "l"(gptr));
}

__global__ __launch_bounds__(256) void flash_attn_tc_kernel(
    const float* __restrict__ qkv, float* __restrict__ att)
{
    extern __shared__ float sm[];
    const int tid  = threadIdx.x;
    const int lane = tid & 31;
    const int w    = tid >> 5;
    const int g    = lane >> 2;
    const int c    = lane & 3;
    const int qb   = (int)gridDim.x - 1 - (int)blockIdx.x;
    const int h    = blockIdx.y;
    const int b    = blockIdx.z;
    const int q0   = qb * AT_BM;
    const size_t base = (size_t)b * SS_ * N_QKV + (size_t)h * HD;
    const float scale = 0.08838834764831845f;

    uint32_t smb;
    asm("{ .reg .u64 t; cvta.to.shared.u64 t, %1; cvt.u32.u64 %0, t; }" : "=r"(smb) : "l"(sm));

#pragma unroll
    for (int i = 0; i < 16; i++) {
        int id = tid + i * 256;
        int r  = id >> 5;
        int c4 = (id & 31) << 2;
        float4 v = *reinterpret_cast<const float4*>(&qkv[base + (size_t)(q0 + r) * N_QKV + c4]);
        int rb = r >> 4, rr = r & 15, gg = rr & 7, half = rr >> 3;
        int ks = c4 >> 3, khalf = (c4 >> 2) & 1;
        int reg = half + 2 * khalf;
        int ba = ((rb * 16 + ks) * 32) * 4 + reg;
        float vv[4] = {v.x, v.y, v.z, v.w};
#pragma unroll
        for (int j = 0; j < 4; j++)
            sm[SM_QF + ba + (gg * 4 + j) * 4] = __uint_as_float(f2tf(vv[j] * scale));
    }

    float o[16][4];
#pragma unroll
    for (int nt = 0; nt < 16; nt++)
#pragma unroll
        for (int l = 0; l < 4; l++) o[nt][l] = 0.f;
    float m0 = -INFINITY, m1 = -INFINITY, l0 = 0.f, l1 = 0.f;

    const int r0 = q0 + w * 16 + g;
    const int nkb = 2 * qb + 2;
    const uint32_t pbase = SM_P + w * (16 * PSTR);

#pragma unroll
    for (int i = 0; i < 8; i++) {
        int id = tid + i * 256;
        int row = id >> 5, c16 = (id & 31) << 2;
        cp16(smb + (uint32_t)(SM_K0 + row * KSTR + c16) * 4,
             &qkv[base + (size_t)row * N_QKV + DD + c16]);
    }
    asm volatile("cp.async.commit_group;");

    for (int kb = 0; kb < nkb; kb++) {
        const int k0 = kb * AT_BN;
        const int sK = (kb & 1) ? SM_K1 : SM_K0;

#pragma unroll
        for (int i = 0; i < 8; i++) {
            int id = tid + i * 256;
            int row = id >> 5, c16 = (id & 31) << 2;
            cp16(smb + (uint32_t)(SM_V + row * VSTR + c16) * 4,
                 &qkv[base + (size_t)(k0 + row) * N_QKV + 2 * DD + c16]);
        }
        asm volatile("cp.async.commit_group;");
        asm volatile("cp.async.wait_group 1;");
        __syncthreads();

        float s[8][4];
#pragma unroll
        for (int nt = 0; nt < 8; nt++)
#pragma unroll
            for (int l = 0; l < 4; l++) s[nt][l] = 0.f;

#pragma unroll
        for (int ks = 0; ks < 16; ks++) {
            float4 qa = *reinterpret_cast<const float4*>(&sm[SM_QF + ((w * 16 + ks) * 32 + lane) * 4]);
            uint32_t a[4] = {__float_as_uint(qa.x), __float_as_uint(qa.y),
                             __float_as_uint(qa.z), __float_as_uint(qa.w)};
#pragma unroll
            for (int nt = 0; nt < 8; nt++) {
                const float* kp = &sm[sK + (nt * 8 + g) * KSTR + ks * 8 + c];
                uint32_t bfr[2] = {f2tf(kp[0]), f2tf(kp[4])};
                mma_tf32(s[nt], a, bfr);
            }
        }

        if (kb + 1 < nkb) {
            const int sKn = (kb & 1) ? SM_K0 : SM_K1;
            const int k0n = (kb + 1) * AT_BN;
#pragma unroll
            for (int i = 0; i < 8; i++) {
                int id = tid + i * 256;
                int row = id >> 5, c16 = (id & 31) << 2;
                cp16(smb + (uint32_t)(sKn + row * KSTR + c16) * 4,
                     &qkv[base + (size_t)(k0n + row) * N_QKV + DD + c16]);
            }
        }
        asm volatile("cp.async.commit_group;");

        if (k0 + 63 > q0 + w * 16) {
#pragma unroll
            for (int nt = 0; nt < 8; nt++) {
                int col = k0 + nt * 8 + 2 * c;
                if (col     > r0)     s[nt][0] = -INFINITY;
                if (col + 1 > r0)     s[nt][1] = -INFINITY;
                if (col     > r0 + 8) s[nt][2] = -INFINITY;
                if (col + 1 > r0 + 8) s[nt][3] = -INFINITY;
            }
        }

        float mt0 = -INFINITY, mt1 = -INFINITY;
#pragma unroll
        for (int nt = 0; nt < 8; nt++) {
            mt0 = fmaxf(mt0, fmaxf(s[nt][0], s[nt][1]));
            mt1 = fmaxf(mt1, fmaxf(s[nt][2], s[nt][3]));
        }
        mt0 = fmaxf(mt0, __shfl_xor_sync(0xffffffffu, mt0, 1));
        mt0 = fmaxf(mt0, __shfl_xor_sync(0xffffffffu, mt0, 2));
        mt1 = fmaxf(mt1, __shfl_xor_sync(0xffffffffu, mt1, 1));
        mt1 = fmaxf(mt1, __shfl_xor_sync(0xffffffffu, mt1, 2));

        float mn0 = fmaxf(m0, mt0), mn1 = fmaxf(m1, mt1);
        float cr0 = __expf(m0 - mn0), cr1 = __expf(m1 - mn1);
        m0 = mn0; m1 = mn1;

        float ps0 = 0.f, ps1 = 0.f;
#pragma unroll
        for (int nt = 0; nt < 8; nt++) {
            float p00 = __expf(s[nt][0] - m0);
            float p01 = __expf(s[nt][1] - m0);
            float p10 = __expf(s[nt][2] - m1);
            float p11 = __expf(s[nt][3] - m1);
            ps0 += p00 + p01;
            ps1 += p10 + p11;
            uint2 u0 = make_uint2(f2tf(p00), f2tf(p01));
            uint2 u1 = make_uint2(f2tf(p10), f2tf(p11));
            *reinterpret_cast<uint2*>(&sm[pbase + g * PSTR + nt * 8 + 2 * c])       = u0;
            *reinterpret_cast<uint2*>(&sm[pbase + (g + 8) * PSTR + nt * 8 + 2 * c]) = u1;
        }
        ps0 += __shfl_xor_sync(0xffffffffu, ps0, 1);
        ps0 += __shfl_xor_sync(0xffffffffu, ps0, 2);
        ps1 += __shfl_xor_sync(0xffffffffu, ps1, 1);
        ps1 += __shfl_xor_sync(0xffffffffu, ps1, 2);
        l0 = l0 * cr0 + ps0;
        l1 = l1 * cr1 + ps1;

#pragma unroll
        for (int nt = 0; nt < 16; nt++) {
            o[nt][0] *= cr0; o[nt][1] *= cr0;
            o[nt][2] *= cr1; o[nt][3] *= cr1;
        }

        asm volatile("cp.async.wait_group 1;");
        __syncthreads();

#pragma unroll
        for (int ks2 = 0; ks2 < 8; ks2++) {
            uint32_t a[4];
            a[0] = __float_as_uint(sm[pbase + g * PSTR + ks2 * 8 + c]);
            a[1] = __float_as_uint(sm[pbase + (g + 8) * PSTR + ks2 * 8 + c]);
            a[2] = __float_as_uint(sm[pbase + g * PSTR + ks2 * 8 + c + 4]);
            a[3] = __float_as_uint(sm[pbase + (g + 8) * PSTR + ks2 * 8 + c + 4]);
#pragma unroll
            for (int nt = 0; nt < 16; nt++) {
                uint32_t bfr[2] = {
                    __float_as_uint(sm[SM_V + (ks2 * 8 + c) * VSTR + nt * 8 + g]),
                    __float_as_uint(sm[SM_V + (ks2 * 8 + c + 4) * VSTR + nt * 8 + g])};
                mma_tf32(o[nt], a, bfr);
            }
        }
        __syncthreads();
    }

    float il0 = 1.f / l0, il1 = 1.f / l1;
    size_t ob = ((size_t)(b * SS_) + q0 + w * 16) * DD + (size_t)h * HD;
#pragma unroll
    for (int nt = 0; nt < 16; nt++) {
        int col = nt * 8 + 2 * c;
        uint2 w0 = make_uint2(f2tf(o[nt][0] * il0), f2tf(o[nt][1] * il0));
        uint2 w1 = make_uint2(f2tf(o[nt][2] * il1), f2tf(o[nt][3] * il1));
        *reinterpret_cast<uint2*>(&att[ob + (size_t)g * DD + col])       = w0;
        *reinterpret_cast<uint2*>(&att[ob + (size_t)(g + 8) * DD + col]) = w1;
    }
}

// ===========================================================================
// Launch
// ===========================================================================
extern "C" void kernel_launch(void* const* d_in, const int* in_sizes, int n_in,
                              void* d_out, int out_size)
{
    const float* x      = (const float*)d_in[0];
    const float* W_qkv  = (const float*)d_in[1];
    const float* b_qkv  = (const float*)d_in[2];
    const float* W_out  = (const float*)d_in[3];
    const float* b_out  = (const float*)d_in[4];
    float* out          = (float*)d_out;

    float *qkv_ptr, *att_ptr, *x_ptr, *w1_ptr, *w2_ptr;
    cudaGetSymbolAddress((void**)&qkv_ptr, g_qkv);
    cudaGetSymbolAddress((void**)&att_ptr, g_att);
    cudaGetSymbolAddress((void**)&x_ptr,  g_x);
    cudaGetSymbolAddress((void**)&w1_ptr, g_w1);
    cudaGetSymbolAddress((void**)&w2_ptr, g_w2);

    cudaFuncSetAttribute(gemm_tf32_kernel,
                         cudaFuncAttributeMaxDynamicSharedMemorySize, GEMM_SMEM_BYTES);
    cudaFuncSetAttribute(flash_attn_tc_kernel,
                         cudaFuncAttributeMaxDynamicSharedMemorySize, AT_SMEM_BYTES);

    // Pre-round operands to tf32 (rna) once
    cvt_tf32_kernel<<<592, 256>>>(x,     x_ptr,  M_TOT * DD / 4);
    cvt_tf32_kernel<<<592, 256>>>(W_qkv, w1_ptr, DD * N_QKV / 4);
    cvt_tf32_kernel<<<592, 256>>>(W_out, w2_ptr, DD * DD / 4);

    // QKV projection: [4096,2048] @ [2048,6144]
    gemm_tf32_kernel<<<dim3(N_QKV / GBN, M_TOT / GBM), 256, GEMM_SMEM_BYTES>>>(
        x_ptr, w1_ptr, b_qkv, qkv_ptr, M_TOT, N_QKV, DD);

    // Fused causal attention (tensor-core)
    flash_attn_tc_kernel<<<dim3(SS_ / AT_BM, HH, BB), 256, AT_SMEM_BYTES>>>(qkv_ptr, att_ptr);

    // Output projection: [4096,2048] @ [2048,2048]
    gemm_tf32_kernel<<<dim3(DD / GBN, M_TOT / GBM), 256, GEMM_SMEM_BYTES>>>(
        att_ptr, w2_ptr, b_out, out, M_TOT, DD, DD);
}